// round 7
// baseline (speedup 1.0000x reference)
#include <cuda_runtime.h>
#include <cstdint>

// SGNN projection, GB300 sm_103a.
//
// per partition p, row b, seed h:
//   v = (sig*seed) mod M, M = 2^31-1 ; center: v>HALF -> v-M ; mean over valid m ; /HALF
//
// Mersenne modulus: prod = hi*2^31 + lo  =>  prod ≡ hi+lo (mod M), s <= 2^32-5 < 2M,
// v = umin(s, s-M).  Centered sum = sum(v) - M * count(v > HALF), and
// v > HALF  <=>  bit30 of v set  (HALF = 2^30 - 1, v < 2^31).
//
// Input dtypes are runtime-detected (int64 vs int32 for sig/seed; u8/i32/f32 for
// mask): int64-encoded values < 2^31 have all-zero odd 32-bit words.

#define BUCKETS_U 2147483647u
#define HALF_F    1073741823.0f

__global__ __launch_bounds__(672)
void sgnn_project_kernel(const void* __restrict__ sig_raw,   // [3,1024,128] int64 OR int32, values in [0, 2^31-1)
                         const void* __restrict__ mask_raw,  // [3,1024,128] bool(u8) OR int32 OR float32
                         const void* __restrict__ seed_raw,  // [672] int64 OR int32, values in [1, 2^31-1)
                         float* __restrict__ out)            // [1024, 672] f32
{
    __shared__ __align__(16) unsigned int s_sig[3][132];  // compacted low-32 sigs, padded to x4
    __shared__ int s_cnt[3];
    __shared__ int s_sig64, s_seed64, s_maskmode;         // detected layouts

    const int b   = blockIdx.x;
    const int tid = threadIdx.x;

    if (tid < 3) s_cnt[tid] = 0;

    if (tid == 0) {
        // --- dtype detection (deterministic, data-driven) ---
        const unsigned int* s32 = (const unsigned int*)sig_raw;
        unsigned int orh = 0;
#pragma unroll
        for (int k = 0; k < 16; ++k) orh |= s32[2 * k + 1];
        s_sig64 = (orh == 0u);   // int64 little-endian: odd words are zero

        const unsigned int* d32 = (const unsigned int*)seed_raw;
        unsigned int orh2 = 0;
#pragma unroll
        for (int k = 0; k < 16; ++k) orh2 |= d32[2 * k + 1];
        s_seed64 = (orh2 == 0u);

        const unsigned char* m8 = (const unsigned char*)mask_raw;
        unsigned int or12 = 0, or3 = 0;
#pragma unroll
        for (int k = 0; k < 32; ++k) {
            or12 |= (unsigned int)m8[4 * k + 1] | (unsigned int)m8[4 * k + 2];
            or3  |= (unsigned int)m8[4 * k + 3];
        }
        int mode;
        if (or12 == 0u && or3 == 0u)                      mode = 1;  // int32 {0,1}
        else if (or12 == 0u && (or3 & ~0x3Fu) == 0u)      mode = 2;  // float32 {0.0f,1.0f}
        else                                              mode = 0;  // uint8 bool
        s_maskmode = mode;
    }
    __syncthreads();

    const int  sig64    = s_sig64;
    const int  seed64   = s_seed64;
    const int  maskmode = s_maskmode;

    // --- cooperative masked compaction: 3 partitions x 128 slots ---
    if (tid < 384) {
        const int p = tid >> 7;
        const int m = tid & 127;
        const size_t idx = ((size_t)p * 1024 + (size_t)b) * 128 + (size_t)m;

        bool valid;
        if (maskmode == 0)      valid = ((const unsigned char*)mask_raw)[idx] != 0;
        else if (maskmode == 1) valid = ((const int*)mask_raw)[idx] != 0;
        else                    valid = ((const float*)mask_raw)[idx] != 0.0f;

        if (valid) {
            const unsigned int* s32 = (const unsigned int*)sig_raw;
            const unsigned int v = sig64 ? s32[2 * idx] : s32[idx];  // low word; value < 2^31
            const int pos = atomicAdd(&s_cnt[p], 1);
            s_sig[p][pos] = v;
        }
    }
    __syncthreads();

    // --- pad each partition to a multiple of 4 with zeros (zero contributes nothing) ---
    if (tid < 3) {
        const int c  = s_cnt[tid];
        const int cp = (c + 3) & ~3;
        for (int k = c; k < cp; ++k) s_sig[tid][k] = 0u;
    }
    __syncthreads();

    // --- per-thread: one seed h, loop over compacted sigs of its partition ---
    const int h = tid;                                   // 0..671
    const int p = (h < 112) ? 0 : ((h < 336) ? 1 : 2);
    const unsigned int* d32 = (const unsigned int*)seed_raw;
    const unsigned int sd = seed64 ? d32[2 * h] : d32[h];  // seed < 2^31
    const int cnt  = s_cnt[p];
    const int cnt4 = (cnt + 3) & ~3;

    unsigned long long acc = 0ull;   // sum of v in [0, M)
    unsigned int nhi = 0u;           // count of v > HALF

    const uint4* sp = (const uint4*)&s_sig[p][0];        // rows are 528B = 16B-aligned

    for (int i = 0; i < cnt4; i += 4) {
        const uint4 q = sp[i >> 2];                      // broadcast LDS.128
        unsigned int xs[4] = {q.x, q.y, q.z, q.w};
#pragma unroll
        for (int j = 0; j < 4; ++j) {
            const unsigned long long prod = (unsigned long long)xs[j] * sd; // IMAD.WIDE.U32
            const unsigned int lo = (unsigned int)prod & 0x7FFFFFFFu;       // LOP3
            const unsigned int hi = (unsigned int)(prod >> 31);             // SHF funnel
            const unsigned int s  = lo + hi;                                // <= 2^32-5 < 2M
            const unsigned int v  = min(s, s - BUCKETS_U);                  // s mod M
            acc += (unsigned long long)v;                                   // IADD3.CC + IADD3.X
            nhi += (v >> 30);                                               // bit30 <=> v > HALF
        }
    }

    const long long centered = (long long)acc - (long long)nhi * 2147483647ll;
    const float cntf = (float)(cnt > 0 ? cnt : 1);
    const float mean = (float)centered / cntf;
    out[(size_t)b * 672 + (size_t)h] = mean * (1.0f / HALF_F);
}

extern "C" void kernel_launch(void* const* d_in, const int* in_sizes, int n_in,
                              void* d_out, int out_size)
{
    (void)in_sizes; (void)n_in; (void)out_size;
    const void* sig  = d_in[0];   // signatures [3,1024,128]
    const void* mask = d_in[1];   // mask       [3,1024,128]
    const void* seed = d_in[2];   // hash_seed  [672]
    float* out = (float*)d_out;   // [1024, 672] f32

    sgnn_project_kernel<<<1024, 672>>>(sig, mask, seed, out);
}

// round 8
// speedup vs baseline: 1.1436x; 1.1436x over previous
#include <cuda_runtime.h>
#include <cstdint>

// SGNN projection, GB300 sm_103a.
//
// per partition p, row b, seed h:
//   v = (sig*seed) mod M, M = 2^31-1 ; center: v>HALF -> v-M ; mean over valid m ; /HALF
//
// Mersenne modulus with seed-doubling: let sd2 = 2*seed. p2 = x*sd2 = 2*x*seed.
//   p2>>32  = (x*seed)>>31            (hi fold term, directly from IMAD.WIDE hi word)
//   p2&mask = 2*((x*seed) mod 2^31)   (lo fold term, pre-doubled)
// s = ((p2.lo)>>1) + p2.hi  computed as  IMAD.HI(p2.lo, 2^31) + p2.hi  (one fma-pipe op)
// s <= 2^32-3 < 2M, so v = umin(s, s-M) = umin(s, s+0x80000001).
// Centered sum = sum(v) - M * count(v > HALF); v>HALF <=> bit30(v), accumulated
// via IMAD.HI(v, 4) (fma pipe).
//
// Input dtypes runtime-detected (int64 vs int32 sig/seed; u8/i32/f32 mask):
// int64-encoded values < 2^31 have all-zero odd 32-bit words.

#define BUCKETS_U 2147483647u
#define HALF_F    1073741823.0f

__global__ __launch_bounds__(672)
void sgnn_project_kernel(const void* __restrict__ sig_raw,   // [3,1024,128]
                         const void* __restrict__ mask_raw,  // [3,1024,128]
                         const void* __restrict__ seed_raw,  // [672]
                         float* __restrict__ out)            // [1024, 672] f32
{
    __shared__ __align__(16) unsigned int s_sig[3][136];  // compacted sigs, padded to x8
    __shared__ int s_cnt[3];
    __shared__ int s_sig64, s_seed64, s_maskmode;

    const int b   = blockIdx.x;
    const int tid = threadIdx.x;

    if (tid < 3) s_cnt[tid] = 0;

    if (tid == 0) {
        // --- dtype detection (deterministic, data-driven) ---
        const unsigned int* s32 = (const unsigned int*)sig_raw;
        unsigned int orh = 0;
#pragma unroll
        for (int k = 0; k < 16; ++k) orh |= s32[2 * k + 1];
        s_sig64 = (orh == 0u);   // int64 little-endian: odd words are zero

        const unsigned int* d32 = (const unsigned int*)seed_raw;
        unsigned int orh2 = 0;
#pragma unroll
        for (int k = 0; k < 16; ++k) orh2 |= d32[2 * k + 1];
        s_seed64 = (orh2 == 0u);

        const unsigned char* m8 = (const unsigned char*)mask_raw;
        unsigned int or12 = 0, or3 = 0;
#pragma unroll
        for (int k = 0; k < 32; ++k) {
            or12 |= (unsigned int)m8[4 * k + 1] | (unsigned int)m8[4 * k + 2];
            or3  |= (unsigned int)m8[4 * k + 3];
        }
        int mode;
        if (or12 == 0u && or3 == 0u)                      mode = 1;  // int32 {0,1}
        else if (or12 == 0u && (or3 & ~0x3Fu) == 0u)      mode = 2;  // float32 {0.0f,1.0f}
        else                                              mode = 0;  // uint8 bool
        s_maskmode = mode;
    }
    __syncthreads();

    const int sig64    = s_sig64;
    const int seed64   = s_seed64;
    const int maskmode = s_maskmode;

    // --- cooperative masked compaction: 3 partitions x 128 slots ---
    if (tid < 384) {
        const int p = tid >> 7;
        const int m = tid & 127;
        const size_t idx = ((size_t)p * 1024 + (size_t)b) * 128 + (size_t)m;

        bool valid;
        if (maskmode == 0)      valid = ((const unsigned char*)mask_raw)[idx] != 0;
        else if (maskmode == 1) valid = ((const int*)mask_raw)[idx] != 0;
        else                    valid = ((const float*)mask_raw)[idx] != 0.0f;

        if (valid) {
            const unsigned int* s32 = (const unsigned int*)sig_raw;
            const unsigned int v = sig64 ? s32[2 * idx] : s32[idx];  // low word; value < 2^31
            const int pos = atomicAdd(&s_cnt[p], 1);
            s_sig[p][pos] = v;
        }
    }
    __syncthreads();

    // --- pad each partition to a multiple of 8 with zeros (zero contributes nothing) ---
    if (tid < 3) {
        const int c  = s_cnt[tid];
        const int cp = (c + 7) & ~7;
        for (int k = c; k < cp; ++k) s_sig[tid][k] = 0u;
    }
    __syncthreads();

    // --- per-thread: one seed h, loop over compacted sigs of its partition ---
    const int h = tid;                                   // 0..671
    const int p = (h < 112) ? 0 : ((h < 336) ? 1 : 2);
    const unsigned int* d32 = (const unsigned int*)seed_raw;
    const unsigned int sd  = seed64 ? d32[2 * h] : d32[h];  // seed in [1, 2^31)
    const unsigned int sd2 = sd + sd;                        // 2*seed < 2^32
    const int cnt  = s_cnt[p];
    const int cnt8 = (cnt + 7) & ~7;

    unsigned long long acc = 0ull;   // sum of v in [0, M)
    unsigned int nhi = 0u;           // count of v > HALF

    const uint4* sp = (const uint4*)&s_sig[p][0];        // rows are 544B = 16B-aligned

    for (int i = 0; i < cnt8; i += 8) {
        const uint4 q0 = sp[(i >> 2) + 0];               // broadcast LDS.128
        const uint4 q1 = sp[(i >> 2) + 1];
        unsigned int xs[8] = {q0.x, q0.y, q0.z, q0.w, q1.x, q1.y, q1.z, q1.w};
#pragma unroll
        for (int j = 0; j < 8; ++j) {
            const unsigned long long p2 = (unsigned long long)xs[j] * sd2; // IMAD.WIDE.U32
            const unsigned int plo = (unsigned int)p2;                     // 2*(prod mod 2^31)
            const unsigned int phi = (unsigned int)(p2 >> 32);             // prod >> 31
            const unsigned int s   = __umulhi(plo, 0x80000000u) + phi;     // IMAD.HI (fma pipe)
            const unsigned int v   = umin(s, s + 0x80000001u);             // IADD3 + IMNMX
            acc += (unsigned long long)v;                                  // 64-bit accumulate
            nhi += __umulhi(v, 4u);                                        // IMAD.HI: += v>>30
        }
    }

    const long long centered = (long long)acc - (long long)nhi * 2147483647ll;
    const float cntf = (float)(cnt > 0 ? cnt : 1);
    const float mean = (float)centered / cntf;
    out[(size_t)b * 672 + (size_t)h] = mean * (1.0f / HALF_F);
}

extern "C" void kernel_launch(void* const* d_in, const int* in_sizes, int n_in,
                              void* d_out, int out_size)
{
    (void)in_sizes; (void)n_in; (void)out_size;
    sgnn_project_kernel<<<1024, 672>>>(d_in[0], d_in[1], d_in[2], (float*)d_out);
}